// round 8
// baseline (speedup 1.0000x reference)
#include <cuda_runtime.h>
#include <cuda_bf16.h>

#define DIMC 1024
#define NHEAD 16
#define HDIM 64
#define BB 4
#define TT 2048
#define MROWS (BB * TT)   // 8192

// Scratch (device globals — allocation-free contract)
__device__ float g_q[BB * NHEAD * TT * HDIM];   // [B,H,T,D]
__device__ float g_k[BB * NHEAD * TT * HDIM];
__device__ float g_v[BB * NHEAD * TT * HDIM];
__device__ float g_att[MROWS * DIMC];           // [B*T, C] attention output
__device__ unsigned g_xc[MROWS * DIMC];         // tf32-rounded x
__device__ unsigned g_wc[4 * DIMC * DIMC];      // tf32-rounded wq|wk|wv|wo

__device__ __forceinline__ unsigned f2tf32(float x) {
    unsigned u;
    asm("cvt.rna.tf32.f32 %0, %1;" : "=r"(u) : "f"(x));
    return u;
}

// 2^x on the FMA/ALU pipes (no MUFU). x <= 0 expected; clamped at -120.
__device__ __forceinline__ float exp2_fast(float x) {
    x = fmaxf(x, -120.f);
    float n = floorf(x);
    float f = x - n;                 // [0,1)
    float p = 1.78656e-4f;           // ~(ln2)^6/720
    p = fmaf(p, f, 1.33336e-3f);
    p = fmaf(p, f, 9.61813e-3f);
    p = fmaf(p, f, 5.55041e-2f);
    p = fmaf(p, f, 2.40226507e-1f);
    p = fmaf(p, f, 6.93147181e-1f);
    p = fmaf(p, f, 1.0f);
    return __uint_as_float(__float_as_uint(p) + (((int)n) << 23));
}

#define MMA_TF32(d, a, b)                                                    \
    asm volatile("mma.sync.aligned.m16n8k8.row.col.f32.tf32.tf32.f32 "        \
                 "{%0,%1,%2,%3}, {%4,%5,%6,%7}, {%8,%9}, {%0,%1,%2,%3};"      \
                 : "+f"(d[0]), "+f"(d[1]), "+f"(d[2]), "+f"(d[3])             \
                 : "r"(a[0]), "r"(a[1]), "r"(a[2]), "r"(a[3]),                \
                   "r"(b[0]), "r"(b[1]))

// ---------------------------------------------------------------------------
// Prepass: tf32-round x and the four weights into unsigned scratch.
// ---------------------------------------------------------------------------
#define XF4  (MROWS * DIMC / 4)        // 2097152
#define WF4  (DIMC * DIMC / 4)         // 262144

__global__ __launch_bounds__(256) void conv_in_kernel(
    const float* __restrict__ x,
    const float* __restrict__ wq, const float* __restrict__ wk,
    const float* __restrict__ wv, const float* __restrict__ wo)
{
    int i = blockIdx.x * 256 + threadIdx.x;     // one float4 per thread
    const float* src;
    unsigned* dst;
    int off;
    if (i < XF4) { src = x; dst = g_xc; off = i; }
    else {
        int j = i - XF4;
        int seg = j >> 18;                       // /262144
        off = j & (WF4 - 1);
        src = seg == 0 ? wq : seg == 1 ? wk : seg == 2 ? wv : wo;
        dst = g_wc + seg * (DIMC * DIMC);
    }
    float4 v = *(const float4*)(src + (size_t)off * 4);
    *(uint4*)(dst + (size_t)off * 4) =
        make_uint4(f2tf32(v.x), f2tf32(v.y), f2tf32(v.z), f2tf32(v.w));
}

// In-place tf32 rounding of g_att (proj A operand). Idempotent.
__global__ __launch_bounds__(256) void conv_att_kernel()
{
    int i = blockIdx.x * 256 + threadIdx.x;
    float4 v = *(const float4*)(g_att + (size_t)i * 4);
    *(uint4*)(g_att + (size_t)i * 4) =
        make_uint4(f2tf32(v.x), f2tf32(v.y), f2tf32(v.z), f2tf32(v.w));
}

// ---------------------------------------------------------------------------
// TF32 tensor-core GEMM: C[M,N] = A[M,K] @ W[N,K]^T, inputs pre-rounded tf32.
// 128x128 block, BK=8, 256 threads (8 warps, 2x4 grid, 64x32/warp).
// Smem rows pair-permuted [k0,k4,k1,k5,k2,k6,k3,k7] so every mma fragment
// pair is one LDS.64 (conflict-free: word = 8*fr + 2*fc spans all banks).
// Staging: threads 0-127 stage A rows, 128-255 stage B rows (LDG.128 x2 +
// STS.128 x2). Double-buffered. qkv_mode scatters to [B,H,T,D].
// ---------------------------------------------------------------------------
__global__ __launch_bounds__(256, 2) void gemm_kernel(
    const unsigned* __restrict__ A,
    const unsigned* __restrict__ W0, const unsigned* __restrict__ W1,
    const unsigned* __restrict__ W2,
    float* __restrict__ D0, float* __restrict__ D1, float* __restrict__ D2,
    int qkv_mode)
{
    __shared__ unsigned As[2][128][8];
    __shared__ unsigned Bs[2][128][8];

    const unsigned* W = W0;
    float* D = D0;
    if (blockIdx.z == 1) { W = W1; D = D1; }
    else if (blockIdx.z == 2) { W = W2; D = D2; }

    const int tid  = threadIdx.x;
    const int lane = tid & 31;
    const int w    = tid >> 5;
    const int wm   = w >> 2;          // 0..1
    const int wn   = w & 3;           // 0..3
    const int r0 = blockIdx.y * 128;
    const int c0 = blockIdx.x * 128;

    const int fr = lane >> 2;            // 0..7
    const int fc = lane & 3;             // 0..3

    // staging: first 128 threads own A rows, next 128 own B rows
    const bool stA = tid < 128;
    const int srow = stA ? tid : tid - 128;
    const unsigned* sp = stA ? (A + (size_t)(r0 + srow) * DIMC)
                             : (W + (size_t)(c0 + srow) * DIMC);

    float acc[4][4][4];
#pragma unroll
    for (int mi = 0; mi < 4; mi++)
#pragma unroll
        for (int ni = 0; ni < 4; ni++)
#pragma unroll
            for (int e = 0; e < 4; e++) acc[mi][ni][e] = 0.f;

    // prologue: stage tile 0 (pair-permuted)
    {
        uint4 v0 = *(const uint4*)(sp);
        uint4 v1 = *(const uint4*)(sp + 4);
        unsigned* dp = stA ? &As[0][srow][0] : &Bs[0][srow][0];
        ((uint4*)dp)[0] = make_uint4(v0.x, v1.x, v0.y, v1.y);
        ((uint4*)dp)[1] = make_uint4(v0.z, v1.z, v0.w, v1.w);
    }
    __syncthreads();

    int buf = 0;
    for (int kt = 1; kt <= DIMC / 8; kt++) {
        uint4 v0, v1;
        const bool more = (kt < DIMC / 8);
        if (more) {
            v0 = *(const uint4*)(sp + kt * 8);
            v1 = *(const uint4*)(sp + kt * 8 + 4);
        }

        // fragments: LDS.64 pairs
        uint2 alo[4], ahi[4], bfp[4];
#pragma unroll
        for (int mi = 0; mi < 4; mi++) {
            int r = wm * 64 + mi * 16 + fr;
            alo[mi] = *(const uint2*)&As[buf][r][2 * fc];
            ahi[mi] = *(const uint2*)&As[buf][r + 8][2 * fc];
        }
#pragma unroll
        for (int ni = 0; ni < 4; ni++) {
            int n = wn * 32 + ni * 8 + fr;
            bfp[ni] = *(const uint2*)&Bs[buf][n][2 * fc];
        }
#pragma unroll
        for (int mi = 0; mi < 4; mi++) {
            unsigned a[4] = {alo[mi].x, ahi[mi].x, alo[mi].y, ahi[mi].y};
#pragma unroll
            for (int ni = 0; ni < 4; ni++) {
                unsigned b[2] = {bfp[ni].x, bfp[ni].y};
                MMA_TF32(acc[mi][ni], a, b);
            }
        }

        if (more) {
            int nb = buf ^ 1;
            unsigned* dp = stA ? &As[nb][srow][0] : &Bs[nb][srow][0];
            ((uint4*)dp)[0] = make_uint4(v0.x, v1.x, v0.y, v1.y);
            ((uint4*)dp)[1] = make_uint4(v0.z, v1.z, v0.w, v1.w);
            __syncthreads();
            buf ^= 1;
        }
    }

    // epilogue
    if (!qkv_mode) {
#pragma unroll
        for (int mi = 0; mi < 4; mi++) {
            int r = r0 + wm * 64 + mi * 16 + fr;
#pragma unroll
            for (int ni = 0; ni < 4; ni++) {
                int c = c0 + wn * 32 + ni * 8 + fc * 2;
                *(float2*)(D + (size_t)r * DIMC + c) =
                    make_float2(acc[mi][ni][0], acc[mi][ni][1]);
                *(float2*)(D + (size_t)(r + 8) * DIMC + c) =
                    make_float2(acc[mi][ni][2], acc[mi][ni][3]);
            }
        }
    } else {
#pragma unroll
        for (int mi = 0; mi < 4; mi++) {
            int row = r0 + wm * 64 + mi * 16 + fr;
#pragma unroll
            for (int half = 0; half < 2; half++) {
                int rr = row + half * 8;
                int b = rr >> 11;
                int t = rr & 2047;
#pragma unroll
                for (int ni = 0; ni < 4; ni++) {
                    int cc = wn * 32 + ni * 8 + fc * 2;
                    int h = blockIdx.x * 2 + (cc >> 6);
                    int d = cc & 63;
                    size_t idx = (((size_t)(b * NHEAD + h) * TT + t) * HDIM) + d;
                    *(float2*)(D + idx) =
                        make_float2(acc[mi][ni][half * 2 + 0],
                                    acc[mi][ni][half * 2 + 1]);
                }
            }
        }
    }
}

// ---------------------------------------------------------------------------
// Flash attention, tensor-core, full-row warps (unchanged from R7).
// BQ=128, BK=64, 256 threads = 8 warps stacked on M; warp owns 16 rows x 64
// cols. Warp-local softmax; warp-private P rows; 2 CTA syncs/tile.
// ---------------------------------------------------------------------------
#define ASTRIDE 68

__global__ __launch_bounds__(256) void attn_kernel()
{
    extern __shared__ unsigned smu[];
    unsigned* Qs = smu;                    // [128][68] tf32, scaled by 0.125*log2e
    unsigned* Ks = Qs + 128 * ASTRIDE;     // [64][68]  tf32, [key][d]
    unsigned* Vt = Ks + 64 * ASTRIDE;      // [64][68]  tf32, [d][key]
    unsigned* Ps = Vt + 64 * ASTRIDE;      // [128][68] tf32 probs (warp-private rows)

    const int tid  = threadIdx.x;
    const int lane = tid & 31;
    const int w    = tid >> 5;        // warp owns rows w*16 .. w*16+15
    const int fr   = lane >> 2;       // 0..7
    const int fc   = lane & 3;        // 0..3

    const int bh = blockIdx.y;
    const int q0 = (gridDim.x - 1 - blockIdx.x) * 128;   // heavy tiles first

    const float* Q = g_q + (size_t)bh * TT * HDIM;
    const float* K = g_k + (size_t)bh * TT * HDIM;
    const float* V = g_v + (size_t)bh * TT * HDIM;

    const float qsc = 0.125f * 1.4426950408889634f;  // scale * log2(e)

    // Stage Q (tf32, scaled): 128 x 64
#pragma unroll
    for (int it = 0; it < 8; it++) {
        int e = tid + it * 256;
        int r = e >> 4, dq = (e & 15) * 4;
        float4 v4 = *(const float4*)(Q + (size_t)(q0 + r) * HDIM + dq);
        unsigned* p = &Qs[r * ASTRIDE + dq];
        p[0] = f2tf32(v4.x * qsc); p[1] = f2tf32(v4.y * qsc);
        p[2] = f2tf32(v4.z * qsc); p[3] = f2tf32(v4.w * qsc);
    }

    float O[8][4];
#pragma unroll
    for (int ni = 0; ni < 8; ni++)
#pragma unroll
        for (int e = 0; e < 4; e++) O[ni][e] = 0.f;
    float m_i[2] = {-1e30f, -1e30f};
    float l_i[2] = {0.f, 0.f};

    const int rbase = w * 16 + fr;
    const int ntiles = (q0 >> 6) + 2;

    for (int kt = 0; kt < ntiles; kt++) {
        const int k0 = kt * 64;
        __syncthreads();

        // Stage K: Ks[key][d]
#pragma unroll
        for (int it = 0; it < 4; it++) {
            int e = tid + it * 256;
            int k = e >> 4, dq = (e & 15) * 4;
            float4 kv = *(const float4*)(K + (size_t)(k0 + k) * HDIM + dq);
            unsigned* p = &Ks[k * ASTRIDE + dq];
            p[0] = f2tf32(kv.x); p[1] = f2tf32(kv.y);
            p[2] = f2tf32(kv.z); p[3] = f2tf32(kv.w);
        }
        // Stage V transposed: Vt[d][key]
#pragma unroll
        for (int it = 0; it < 4; it++) {
            int e = tid + it * 256;
            int d = e & 63;
            int kq = (e >> 6) * 4;
            float v0 = V[(size_t)(k0 + kq + 0) * HDIM + d];
            float v1 = V[(size_t)(k0 + kq + 1) * HDIM + d];
            float v2 = V[(size_t)(k0 + kq + 2) * HDIM + d];
            float v3 = V[(size_t)(k0 + kq + 3) * HDIM + d];
            *(uint4*)&Vt[d * ASTRIDE + kq] =
                make_uint4(f2tf32(v0), f2tf32(v1), f2tf32(v2), f2tf32(v3));
        }
        __syncthreads();

        // S = Qs @ Ks^T : warp computes 16 rows x 64 cols
        float sacc[8][4];
#pragma unroll
        for (int ni = 0; ni < 8; ni++)
#pragma unroll
            for (int e = 0; e < 4; e++) sacc[ni][e] = 0.f;

#pragma unroll
        for (int kk = 0; kk < 8; kk++) {
            unsigned af[4];
            {
                const unsigned* b = &Qs[rbase * ASTRIDE + kk * 8 + fc];
                af[0] = b[0];
                af[1] = b[8 * ASTRIDE];
                af[2] = b[4];
                af[3] = b[8 * ASTRIDE + 4];
            }
#pragma unroll
            for (int ni = 0; ni < 8; ni++) {
                const unsigned* b = &Ks[(ni * 8 + fr) * ASTRIDE + kk * 8 + fc];
                unsigned bf[2] = {b[0], b[4]};
                MMA_TF32(sacc[ni], af, bf);
            }
        }

        // Warp-local softmax (log2 domain)
        const bool need_mask = (k0 + 63 > q0);
#pragma unroll
        for (int h = 0; h < 2; h++) {
            const int rg = q0 + rbase + h * 8;
            float rm = -1e30f;
#pragma unroll
            for (int ni = 0; ni < 8; ni++)
#pragma unroll
            for (int e = 0; e < 2; e++) {
                float s = sacc[ni][h * 2 + e];
                if (need_mask && (k0 + ni * 8 + fc * 2 + e > rg)) s = -1e30f;
                sacc[ni][h * 2 + e] = s;
                rm = fmaxf(rm, s);
            }
            rm = fmaxf(rm, __shfl_xor_sync(0xffffffffu, rm, 1));
            rm = fmaxf(rm, __shfl_xor_sync(0xffffffffu, rm, 2));
            float mnew = fmaxf(m_i[h], rm);
            float al = exp2_fast(m_i[h] - mnew);
            m_i[h] = mnew;
            float rs = 0.f;
#pragma unroll
            for (int ni = 0; ni < 8; ni++) {
                float p0 = exp2_fast(sacc[ni][h * 2 + 0] - mnew);
                float p1 = exp2_fast(sacc[ni][h * 2 + 1] - mnew);
                rs += p0 + p1;
                *(uint2*)&Ps[(rbase + h * 8) * ASTRIDE + ni * 8 + fc * 2] =
                    make_uint2(f2tf32(p0), f2tf32(p1));
            }
            rs += __shfl_xor_sync(0xffffffffu, rs, 1);
            rs += __shfl_xor_sync(0xffffffffu, rs, 2);
            l_i[h] = l_i[h] * al + rs;
#pragma unroll
            for (int ni = 0; ni < 8; ni++) {
                O[ni][h * 2 + 0] *= al;
                O[ni][h * 2 + 1] *= al;
            }
        }
        __syncwarp();

        // O += P @ V
#pragma unroll
        for (int kk = 0; kk < 8; kk++) {
            unsigned af[4];
            {
                const unsigned* b = &Ps[rbase * ASTRIDE + kk * 8 + fc];
                af[0] = b[0];
                af[1] = b[8 * ASTRIDE];
                af[2] = b[4];
                af[3] = b[8 * ASTRIDE + 4];
            }
#pragma unroll
            for (int ni = 0; ni < 8; ni++) {
                const unsigned* b = &Vt[(ni * 8 + fr) * ASTRIDE + kk * 8 + fc];
                unsigned bf[2] = {b[0], b[4]};
                MMA_TF32(O[ni], af, bf);
            }
        }
    }

    // Epilogue: normalize, store to [B*T, C]
    const int b = bh >> 4;
    const int h = bh & 15;
#pragma unroll
    for (int hh = 0; hh < 2; hh++) {
        float linv = 1.0f / l_i[hh];
        int row = q0 + rbase + hh * 8;
        float* op = g_att + ((size_t)(b * TT) + row) * DIMC + h * HDIM;
#pragma unroll
        for (int ni = 0; ni < 8; ni++) {
            *(float2*)(op + ni * 8 + fc * 2) =
                make_float2(O[ni][hh * 2 + 0] * linv,
                            O[ni][hh * 2 + 1] * linv);
        }
    }
}

#define ATTN_SMEM_BYTES ((128*ASTRIDE + 64*ASTRIDE + 64*ASTRIDE + 128*ASTRIDE) * 4)

// ---------------------------------------------------------------------------
extern "C" void kernel_launch(void* const* d_in, const int* in_sizes, int n_in,
                              void* d_out, int out_size)
{
    const float* x  = (const float*)d_in[0];
    // d_in[1] = mask (unused; causal applied analytically)
    const float* wq = (const float*)d_in[2];
    const float* wk = (const float*)d_in[3];
    const float* wv = (const float*)d_in[4];
    const float* wo = (const float*)d_in[5];
    float* out = (float*)d_out;

    float *dq, *dk, *dv, *datt;
    unsigned *dxc, *dwc;
    cudaGetSymbolAddress((void**)&dq,   g_q);
    cudaGetSymbolAddress((void**)&dk,   g_k);
    cudaGetSymbolAddress((void**)&dv,   g_v);
    cudaGetSymbolAddress((void**)&datt, g_att);
    cudaGetSymbolAddress((void**)&dxc,  g_xc);
    cudaGetSymbolAddress((void**)&dwc,  g_wc);

    cudaFuncSetAttribute(attn_kernel,
                         cudaFuncAttributeMaxDynamicSharedMemorySize,
                         ATTN_SMEM_BYTES);

    // Prepass: round x + weights to tf32
    conv_in_kernel<<<(XF4 + 4 * WF4) / 256, 256>>>(x, wq, wk, wv, wo);

    // QKV projections: 128x128 tiles, grid (8, 64, 3)
    gemm_kernel<<<dim3(8, 64, 3), 256>>>(
        dxc, dwc, dwc + DIMC * DIMC, dwc + 2 * DIMC * DIMC,
        dq, dk, dv, 1);

    // Flash attention: grid (16 q-tiles, 64 b*h)
    attn_kernel<<<dim3(16, 64), 256, ATTN_SMEM_BYTES>>>();

    // Round attention output in place (proj A operand)
    conv_att_kernel<<<XF4 / 256, 256>>>();

    // Output projection
    gemm_kernel<<<dim3(8, 64, 1), 256>>>(
        (unsigned*)datt, dwc + 3 * DIMC * DIMC, nullptr, nullptr,
        out, nullptr, nullptr, 0);
}

// round 9
// speedup vs baseline: 1.1699x; 1.1699x over previous
#include <cuda_runtime.h>
#include <cuda_bf16.h>

#define DIMC 1024
#define NHEAD 16
#define HDIM 64
#define BB 4
#define TT 2048
#define MROWS (BB * TT)   // 8192

// Scratch (device globals — allocation-free contract)
__device__ float g_q[BB * NHEAD * TT * HDIM];   // [B,H,T,D]
__device__ float g_k[BB * NHEAD * TT * HDIM];
__device__ float g_v[BB * NHEAD * TT * HDIM];
__device__ float g_att[MROWS * DIMC];           // [B*T, C] attn out (tf32 bits)
__device__ unsigned g_xc[MROWS * DIMC];         // tf32-rounded x
__device__ unsigned g_wc[4 * DIMC * DIMC];      // tf32-rounded wq|wk|wv|wo

__device__ __forceinline__ unsigned f2tf32(float x) {
    unsigned u;
    asm("cvt.rna.tf32.f32 %0, %1;" : "=r"(u) : "f"(x));
    return u;
}

// 2^x on the FMA/ALU pipes (no MUFU). x <= 0 expected; clamped at -120.
__device__ __forceinline__ float exp2_fast(float x) {
    x = fmaxf(x, -120.f);
    float n = floorf(x);
    float f = x - n;                 // [0,1)
    float p = 1.78656e-4f;           // ~(ln2)^6/720
    p = fmaf(p, f, 1.33336e-3f);
    p = fmaf(p, f, 9.61813e-3f);
    p = fmaf(p, f, 5.55041e-2f);
    p = fmaf(p, f, 2.40226507e-1f);
    p = fmaf(p, f, 6.93147181e-1f);
    p = fmaf(p, f, 1.0f);
    return __uint_as_float(__float_as_uint(p) + (((int)n) << 23));
}

#define MMA_TF32(d, a, b)                                                    \
    asm volatile("mma.sync.aligned.m16n8k8.row.col.f32.tf32.tf32.f32 "        \
                 "{%0,%1,%2,%3}, {%4,%5,%6,%7}, {%8,%9}, {%0,%1,%2,%3};"      \
                 : "+f"(d[0]), "+f"(d[1]), "+f"(d[2]), "+f"(d[3])             \
                 : "r"(a[0]), "r"(a[1]), "r"(a[2]), "r"(a[3]),                \
                   "r"(b[0]), "r"(b[1]))

// ---------------------------------------------------------------------------
// Prepass: tf32-round x and the four weights into unsigned scratch.
// ---------------------------------------------------------------------------
#define XF4  (MROWS * DIMC / 4)        // 2097152
#define WF4  (DIMC * DIMC / 4)         // 262144

__global__ __launch_bounds__(256) void conv_in_kernel(
    const float* __restrict__ x,
    const float* __restrict__ wq, const float* __restrict__ wk,
    const float* __restrict__ wv, const float* __restrict__ wo)
{
    int i = blockIdx.x * 256 + threadIdx.x;     // one float4 per thread
    const float* src;
    unsigned* dst;
    int off;
    if (i < XF4) { src = x; dst = g_xc; off = i; }
    else {
        int j = i - XF4;
        int seg = j >> 18;                       // /262144
        off = j & (WF4 - 1);
        src = seg == 0 ? wq : seg == 1 ? wk : seg == 2 ? wv : wo;
        dst = g_wc + seg * (DIMC * DIMC);
    }
    float4 v = *(const float4*)(src + (size_t)off * 4);
    *(uint4*)(dst + (size_t)off * 4) =
        make_uint4(f2tf32(v.x), f2tf32(v.y), f2tf32(v.z), f2tf32(v.w));
}

// ---------------------------------------------------------------------------
// TF32 tensor-core GEMM: C[M,N] = A[M,K] @ W[N,K]^T, inputs pre-rounded tf32.
// 128x128 block, BK=16 per stage, 256 threads (8 warps, 2x4 grid, 64x32/warp),
// k-major KSTRIDE=136 smem (R7 bank-clean layout), double-buffered.
// One barrier per 32 MMAs/warp. qkv_mode scatters to [B,H,T,D].
// ---------------------------------------------------------------------------
#define KSTRIDE 136

__global__ __launch_bounds__(256, 2) void gemm_kernel(
    const unsigned* __restrict__ A,
    const unsigned* __restrict__ W0, const unsigned* __restrict__ W1,
    const unsigned* __restrict__ W2,
    float* __restrict__ D0, float* __restrict__ D1, float* __restrict__ D2,
    int qkv_mode)
{
    __shared__ unsigned As[2][16][KSTRIDE];
    __shared__ unsigned Bs[2][16][KSTRIDE];

    const unsigned* W = W0;
    float* D = D0;
    if (blockIdx.z == 1) { W = W1; D = D1; }
    else if (blockIdx.z == 2) { W = W2; D = D2; }

    const int tid  = threadIdx.x;
    const int lane = tid & 31;
    const int w    = tid >> 5;
    const int wm   = w >> 2;          // 0..1
    const int wn   = w & 3;           // 0..3
    const int r0 = blockIdx.y * 128;
    const int c0 = blockIdx.x * 128;

    const int lrow = tid >> 1;           // 0..127
    const int lk   = (tid & 1) * 8;      // 0 or 8
    const unsigned* Ap = A + (size_t)(r0 + lrow) * DIMC + lk;
    const unsigned* Wp = W + (size_t)(c0 + lrow) * DIMC + lk;

    const int fr = lane >> 2;            // 0..7
    const int fc = lane & 3;             // 0..3

    float acc[4][4][4];
#pragma unroll
    for (int mi = 0; mi < 4; mi++)
#pragma unroll
        for (int ni = 0; ni < 4; ni++)
#pragma unroll
            for (int e = 0; e < 4; e++) acc[mi][ni][e] = 0.f;

    // prologue: stage tile 0
    {
        uint4 a0 = *(const uint4*)(Ap);
        uint4 a1 = *(const uint4*)(Ap + 4);
        uint4 b0 = *(const uint4*)(Wp);
        uint4 b1 = *(const uint4*)(Wp + 4);
        As[0][lk + 0][lrow] = a0.x; As[0][lk + 1][lrow] = a0.y;
        As[0][lk + 2][lrow] = a0.z; As[0][lk + 3][lrow] = a0.w;
        As[0][lk + 4][lrow] = a1.x; As[0][lk + 5][lrow] = a1.y;
        As[0][lk + 6][lrow] = a1.z; As[0][lk + 7][lrow] = a1.w;
        Bs[0][lk + 0][lrow] = b0.x; Bs[0][lk + 1][lrow] = b0.y;
        Bs[0][lk + 2][lrow] = b0.z; Bs[0][lk + 3][lrow] = b0.w;
        Bs[0][lk + 4][lrow] = b1.x; Bs[0][lk + 5][lrow] = b1.y;
        Bs[0][lk + 6][lrow] = b1.z; Bs[0][lk + 7][lrow] = b1.w;
    }
    __syncthreads();

    int buf = 0;
    for (int kt = 1; kt <= DIMC / 16; kt++) {
        uint4 a0, a1, b0, b1;
        const bool more = (kt < DIMC / 16);
        if (more) {
            a0 = *(const uint4*)(Ap + kt * 16);
            a1 = *(const uint4*)(Ap + kt * 16 + 4);
            b0 = *(const uint4*)(Wp + kt * 16);
            b1 = *(const uint4*)(Wp + kt * 16 + 4);
        }

#pragma unroll
        for (int kk = 0; kk < 2; kk++) {
            unsigned af[4][4], bfr[4][2];
#pragma unroll
            for (int mi = 0; mi < 4; mi++) {
                int r = wm * 64 + mi * 16 + fr;
                af[mi][0] = As[buf][kk * 8 + fc][r];
                af[mi][1] = As[buf][kk * 8 + fc][r + 8];
                af[mi][2] = As[buf][kk * 8 + fc + 4][r];
                af[mi][3] = As[buf][kk * 8 + fc + 4][r + 8];
            }
#pragma unroll
            for (int ni = 0; ni < 4; ni++) {
                int n = wn * 32 + ni * 8 + fr;
                bfr[ni][0] = Bs[buf][kk * 8 + fc][n];
                bfr[ni][1] = Bs[buf][kk * 8 + fc + 4][n];
            }
#pragma unroll
            for (int mi = 0; mi < 4; mi++)
#pragma unroll
                for (int ni = 0; ni < 4; ni++)
                    MMA_TF32(acc[mi][ni], af[mi], bfr[ni]);
        }

        if (more) {
            int nb = buf ^ 1;
            As[nb][lk + 0][lrow] = a0.x; As[nb][lk + 1][lrow] = a0.y;
            As[nb][lk + 2][lrow] = a0.z; As[nb][lk + 3][lrow] = a0.w;
            As[nb][lk + 4][lrow] = a1.x; As[nb][lk + 5][lrow] = a1.y;
            As[nb][lk + 6][lrow] = a1.z; As[nb][lk + 7][lrow] = a1.w;
            Bs[nb][lk + 0][lrow] = b0.x; Bs[nb][lk + 1][lrow] = b0.y;
            Bs[nb][lk + 2][lrow] = b0.z; Bs[nb][lk + 3][lrow] = b0.w;
            Bs[nb][lk + 4][lrow] = b1.x; Bs[nb][lk + 5][lrow] = b1.y;
            Bs[nb][lk + 6][lrow] = b1.z; Bs[nb][lk + 7][lrow] = b1.w;
            __syncthreads();
            buf ^= 1;
        }
    }

    // epilogue
    if (!qkv_mode) {
#pragma unroll
        for (int mi = 0; mi < 4; mi++) {
            int r = r0 + wm * 64 + mi * 16 + fr;
#pragma unroll
            for (int ni = 0; ni < 4; ni++) {
                int c = c0 + wn * 32 + ni * 8 + fc * 2;
                *(float2*)(D + (size_t)r * DIMC + c) =
                    make_float2(acc[mi][ni][0], acc[mi][ni][1]);
                *(float2*)(D + (size_t)(r + 8) * DIMC + c) =
                    make_float2(acc[mi][ni][2], acc[mi][ni][3]);
            }
        }
    } else {
#pragma unroll
        for (int mi = 0; mi < 4; mi++) {
            int row = r0 + wm * 64 + mi * 16 + fr;
#pragma unroll
            for (int half = 0; half < 2; half++) {
                int rr = row + half * 8;
                int b = rr >> 11;
                int t = rr & 2047;
#pragma unroll
                for (int ni = 0; ni < 4; ni++) {
                    int cc = wn * 32 + ni * 8 + fc * 2;
                    int h = blockIdx.x * 2 + (cc >> 6);
                    int d = cc & 63;
                    size_t idx = (((size_t)(b * NHEAD + h) * TT + t) * HDIM) + d;
                    *(float2*)(D + idx) =
                        make_float2(acc[mi][ni][half * 2 + 0],
                                    acc[mi][ni][half * 2 + 1]);
                }
            }
        }
    }
}

// ---------------------------------------------------------------------------
// Flash attention, tensor-core, full-row warps (R7 version; epilogue now
// stores tf32-rounded bits so the output projection needs no conv pass).
// ---------------------------------------------------------------------------
#define ASTRIDE 68

__global__ __launch_bounds__(256) void attn_kernel()
{
    extern __shared__ unsigned smu[];
    unsigned* Qs = smu;                    // [128][68] tf32, scaled by 0.125*log2e
    unsigned* Ks = Qs + 128 * ASTRIDE;     // [64][68]  tf32, [key][d]
    unsigned* Vt = Ks + 64 * ASTRIDE;      // [64][68]  tf32, [d][key]
    unsigned* Ps = Vt + 64 * ASTRIDE;      // [128][68] tf32 probs (warp-private rows)

    const int tid  = threadIdx.x;
    const int lane = tid & 31;
    const int w    = tid >> 5;        // warp owns rows w*16 .. w*16+15
    const int fr   = lane >> 2;       // 0..7
    const int fc   = lane & 3;        // 0..3

    const int bh = blockIdx.y;
    const int q0 = (gridDim.x - 1 - blockIdx.x) * 128;   // heavy tiles first

    const float* Q = g_q + (size_t)bh * TT * HDIM;
    const float* K = g_k + (size_t)bh * TT * HDIM;
    const float* V = g_v + (size_t)bh * TT * HDIM;

    const float qsc = 0.125f * 1.4426950408889634f;  // scale * log2(e)

    // Stage Q (tf32, scaled): 128 x 64
#pragma unroll
    for (int it = 0; it < 8; it++) {
        int e = tid + it * 256;
        int r = e >> 4, dq = (e & 15) * 4;
        float4 v4 = *(const float4*)(Q + (size_t)(q0 + r) * HDIM + dq);
        unsigned* p = &Qs[r * ASTRIDE + dq];
        p[0] = f2tf32(v4.x * qsc); p[1] = f2tf32(v4.y * qsc);
        p[2] = f2tf32(v4.z * qsc); p[3] = f2tf32(v4.w * qsc);
    }

    float O[8][4];
#pragma unroll
    for (int ni = 0; ni < 8; ni++)
#pragma unroll
        for (int e = 0; e < 4; e++) O[ni][e] = 0.f;
    float m_i[2] = {-1e30f, -1e30f};
    float l_i[2] = {0.f, 0.f};

    const int rbase = w * 16 + fr;
    const int ntiles = (q0 >> 6) + 2;

    for (int kt = 0; kt < ntiles; kt++) {
        const int k0 = kt * 64;
        __syncthreads();

        // Stage K: Ks[key][d]
#pragma unroll
        for (int it = 0; it < 4; it++) {
            int e = tid + it * 256;
            int k = e >> 4, dq = (e & 15) * 4;
            float4 kv = *(const float4*)(K + (size_t)(k0 + k) * HDIM + dq);
            unsigned* p = &Ks[k * ASTRIDE + dq];
            p[0] = f2tf32(kv.x); p[1] = f2tf32(kv.y);
            p[2] = f2tf32(kv.z); p[3] = f2tf32(kv.w);
        }
        // Stage V transposed: Vt[d][key]
#pragma unroll
        for (int it = 0; it < 4; it++) {
            int e = tid + it * 256;
            int d = e & 63;
            int kq = (e >> 6) * 4;
            float v0 = V[(size_t)(k0 + kq + 0) * HDIM + d];
            float v1 = V[(size_t)(k0 + kq + 1) * HDIM + d];
            float v2 = V[(size_t)(k0 + kq + 2) * HDIM + d];
            float v3 = V[(size_t)(k0 + kq + 3) * HDIM + d];
            *(uint4*)&Vt[d * ASTRIDE + kq] =
                make_uint4(f2tf32(v0), f2tf32(v1), f2tf32(v2), f2tf32(v3));
        }
        __syncthreads();

        // S = Qs @ Ks^T : warp computes 16 rows x 64 cols
        float sacc[8][4];
#pragma unroll
        for (int ni = 0; ni < 8; ni++)
#pragma unroll
            for (int e = 0; e < 4; e++) sacc[ni][e] = 0.f;

#pragma unroll
        for (int kk = 0; kk < 8; kk++) {
            unsigned af[4];
            {
                const unsigned* b = &Qs[rbase * ASTRIDE + kk * 8 + fc];
                af[0] = b[0];
                af[1] = b[8 * ASTRIDE];
                af[2] = b[4];
                af[3] = b[8 * ASTRIDE + 4];
            }
#pragma unroll
            for (int ni = 0; ni < 8; ni++) {
                const unsigned* b = &Ks[(ni * 8 + fr) * ASTRIDE + kk * 8 + fc];
                unsigned bf[2] = {b[0], b[4]};
                MMA_TF32(sacc[ni], af, bf);
            }
        }

        // Warp-local softmax (log2 domain)
        const bool need_mask = (k0 + 63 > q0);
#pragma unroll
        for (int h = 0; h < 2; h++) {
            const int rg = q0 + rbase + h * 8;
            float rm = -1e30f;
#pragma unroll
            for (int ni = 0; ni < 8; ni++)
#pragma unroll
            for (int e = 0; e < 2; e++) {
                float s = sacc[ni][h * 2 + e];
                if (need_mask && (k0 + ni * 8 + fc * 2 + e > rg)) s = -1e30f;
                sacc[ni][h * 2 + e] = s;
                rm = fmaxf(rm, s);
            }
            rm = fmaxf(rm, __shfl_xor_sync(0xffffffffu, rm, 1));
            rm = fmaxf(rm, __shfl_xor_sync(0xffffffffu, rm, 2));
            float mnew = fmaxf(m_i[h], rm);
            float al = exp2_fast(m_i[h] - mnew);
            m_i[h] = mnew;
            float rs = 0.f;
#pragma unroll
            for (int ni = 0; ni < 8; ni++) {
                float p0 = exp2_fast(sacc[ni][h * 2 + 0] - mnew);
                float p1 = exp2_fast(sacc[ni][h * 2 + 1] - mnew);
                rs += p0 + p1;
                *(uint2*)&Ps[(rbase + h * 8) * ASTRIDE + ni * 8 + fc * 2] =
                    make_uint2(f2tf32(p0), f2tf32(p1));
            }
            rs += __shfl_xor_sync(0xffffffffu, rs, 1);
            rs += __shfl_xor_sync(0xffffffffu, rs, 2);
            l_i[h] = l_i[h] * al + rs;
#pragma unroll
            for (int ni = 0; ni < 8; ni++) {
                O[ni][h * 2 + 0] *= al;
                O[ni][h * 2 + 1] *= al;
            }
        }
        __syncwarp();

        // O += P @ V
#pragma unroll
        for (int kk = 0; kk < 8; kk++) {
            unsigned af[4];
            {
                const unsigned* b = &Ps[rbase * ASTRIDE + kk * 8 + fc];
                af[0] = b[0];
                af[1] = b[8 * ASTRIDE];
                af[2] = b[4];
                af[3] = b[8 * ASTRIDE + 4];
            }
#pragma unroll
            for (int ni = 0; ni < 8; ni++) {
                const unsigned* b = &Vt[(ni * 8 + fr) * ASTRIDE + kk * 8 + fc];
                unsigned bf[2] = {b[0], b[4]};
                MMA_TF32(O[ni], af, bf);
            }
        }
    }

    // Epilogue: normalize, store tf32-rounded bits to [B*T, C]
    const int b = bh >> 4;
    const int h = bh & 15;
#pragma unroll
    for (int hh = 0; hh < 2; hh++) {
        float linv = 1.0f / l_i[hh];
        int row = q0 + rbase + hh * 8;
        unsigned* op = (unsigned*)g_att + ((size_t)(b * TT) + row) * DIMC + h * HDIM;
#pragma unroll
        for (int ni = 0; ni < 8; ni++) {
            *(uint2*)(op + ni * 8 + fc * 2) =
                make_uint2(f2tf32(O[ni][hh * 2 + 0] * linv),
                           f2tf32(O[ni][hh * 2 + 1] * linv));
        }
    }
}

#define ATTN_SMEM_BYTES ((128*ASTRIDE + 64*ASTRIDE + 64*ASTRIDE + 128*ASTRIDE) * 4)

// ---------------------------------------------------------------------------
extern "C" void kernel_launch(void* const* d_in, const int* in_sizes, int n_in,
                              void* d_out, int out_size)
{
    const float* x  = (const float*)d_in[0];
    // d_in[1] = mask (unused; causal applied analytically)
    const float* wq = (const float*)d_in[2];
    const float* wk = (const float*)d_in[3];
    const float* wv = (const float*)d_in[4];
    const float* wo = (const float*)d_in[5];
    float* out = (float*)d_out;

    float *dq, *dk, *dv, *datt;
    unsigned *dxc, *dwc;
    cudaGetSymbolAddress((void**)&dq,   g_q);
    cudaGetSymbolAddress((void**)&dk,   g_k);
    cudaGetSymbolAddress((void**)&dv,   g_v);
    cudaGetSymbolAddress((void**)&datt, g_att);
    cudaGetSymbolAddress((void**)&dxc,  g_xc);
    cudaGetSymbolAddress((void**)&dwc,  g_wc);

    cudaFuncSetAttribute(attn_kernel,
                         cudaFuncAttributeMaxDynamicSharedMemorySize,
                         ATTN_SMEM_BYTES);

    // Prepass: round x + weights to tf32
    conv_in_kernel<<<(XF4 + 4 * WF4) / 256, 256>>>(x, wq, wk, wv, wo);

    // QKV projections: 128x128 tiles, grid (8, 64, 3)
    gemm_kernel<<<dim3(8, 64, 3), 256>>>(
        dxc, dwc, dwc + DIMC * DIMC, dwc + 2 * DIMC * DIMC,
        dq, dk, dv, 1);

    // Flash attention: grid (16 q-tiles, 64 b*h)
    attn_kernel<<<dim3(16, 64), 256, ATTN_SMEM_BYTES>>>();

    // Output projection (g_att already holds tf32 bits)
    gemm_kernel<<<dim3(8, 64, 1), 256>>>(
        (unsigned*)datt, dwc + 3 * DIMC * DIMC, nullptr, nullptr,
        out, nullptr, nullptr, 0);
}